// round 2
// baseline (speedup 1.0000x reference)
#include <cuda_runtime.h>
#include <cstdint>

// ---------------------------------------------------------------------------
// pointwise (Bahdanau additive) attention, fp32, fused score GEMM via f32x2
// B=32, T=2048, D=512, U=512
// out layout: [0, B*D)  = context ; [B*D, B*D + B*T) = attn
// ---------------------------------------------------------------------------

#define TILE_M 128
#define TILE_N 128
#define TILE_K 16
#define AS_LD  264   // duplicated A tile leading dim (2*132), 16B-aligned rows
#define BS_LD  132   // B tile leading dim, 16B-aligned rows

// scratch (allocation-free rule: __device__ globals)
__device__ float g_scores[32 * 2048];     // B*T raw e2 accumulators
__device__ float g_dec_proj[32 * 512];    // B*U  (h_dec @ W1_dec + b1)

// -------------------- packed f32x2 helpers --------------------
__device__ __forceinline__ unsigned long long ffma2(unsigned long long a,
                                                    unsigned long long b,
                                                    unsigned long long c) {
    unsigned long long d;
    asm("fma.rn.f32x2 %0, %1, %2, %3;" : "=l"(d) : "l"(a), "l"(b), "l"(c));
    return d;
}
__device__ __forceinline__ float2 unpack2(unsigned long long v) {
    float2 f;
    asm("mov.b64 {%0, %1}, %2;" : "=f"(f.x), "=f"(f.y) : "l"(v));
    return f;
}

// -------------------- kernel 1: dec projection + zero scores --------------------
__global__ void prep_kernel(const float* __restrict__ h_dec,
                            const float* __restrict__ W1,
                            const float* __restrict__ b1,
                            int B, int T, int D, int U) {
    const int b = blockIdx.x;
    __shared__ float hd[512];
    for (int i = threadIdx.x; i < D; i += blockDim.x) hd[i] = h_dec[b * D + i];
    __syncthreads();

    for (int u = threadIdx.x; u < U; u += blockDim.x) {
        float acc0 = b1[u], acc1 = 0.f, acc2 = 0.f, acc3 = 0.f;
        int k = 0;
        for (; k + 3 < D; k += 4) {
            acc0 += hd[k + 0] * W1[(size_t)(D + k + 0) * U + u];
            acc1 += hd[k + 1] * W1[(size_t)(D + k + 1) * U + u];
            acc2 += hd[k + 2] * W1[(size_t)(D + k + 2) * U + u];
            acc3 += hd[k + 3] * W1[(size_t)(D + k + 3) * U + u];
        }
        for (; k < D; k++) acc0 += hd[k] * W1[(size_t)(D + k) * U + u];
        g_dec_proj[b * U + u] = (acc0 + acc1) + (acc2 + acc3);
    }
    // zero this batch's score row (graph replays need this every launch)
    for (int t = threadIdx.x; t < T; t += blockDim.x) g_scores[b * T + t] = 0.f;
}

// -------------------- kernel 2: fused score GEMM --------------------
// scores[b,t] += sum_{u in tile} tanh( (h_enc[b,t,:] @ W1_enc[:,u]) + dec_proj[b,u] ) * W2[u]
__global__ __launch_bounds__(256, 2)
void score_kernel(const float* __restrict__ h_enc,
                  const float* __restrict__ W1,
                  const float* __restrict__ W2,
                  int B, int T, int D, int U) {
    __shared__ float As[TILE_K * AS_LD];   // duplicated: As[k][2m]=As[k][2m+1]=A[m][k]
    __shared__ float Bs[TILE_K * BS_LD];   // Bs[k][u]

    const int tid = threadIdx.x;
    const int tx  = tid & 15;              // n-direction (8 floats = 4 pairs)
    const int ty  = tid >> 4;              // m-direction (8 rows)
    const int b   = blockIdx.y;
    const int t0  = blockIdx.x * TILE_M;
    const int u0  = blockIdx.z * TILE_N;

    const float* Ag = h_enc + ((size_t)b * T + t0) * D;
    const float* Bg = W1 + u0;

    unsigned long long acc[8][4];
#pragma unroll
    for (int i = 0; i < 8; i++)
#pragma unroll
        for (int j = 0; j < 4; j++) acc[i][j] = 0ULL;

    for (int k0 = 0; k0 < D; k0 += TILE_K) {
        // ---- load A tile (128 rows x 16 k), store transposed + duplicated ----
#pragma unroll
        for (int q = 0; q < 2; q++) {
            int idx = q * 256 + tid;
            int row = idx >> 2;            // 0..127
            int col = (idx & 3) * 4;       // 0,4,8,12
            float4 v = *(const float4*)(Ag + (size_t)row * D + k0 + col);
            As[(col + 0) * AS_LD + 2 * row] = v.x; As[(col + 0) * AS_LD + 2 * row + 1] = v.x;
            As[(col + 1) * AS_LD + 2 * row] = v.y; As[(col + 1) * AS_LD + 2 * row + 1] = v.y;
            As[(col + 2) * AS_LD + 2 * row] = v.z; As[(col + 2) * AS_LD + 2 * row + 1] = v.z;
            As[(col + 3) * AS_LD + 2 * row] = v.w; As[(col + 3) * AS_LD + 2 * row + 1] = v.w;
        }
        // ---- load B tile (16 k x 128 u) ----
#pragma unroll
        for (int q = 0; q < 2; q++) {
            int idx = q * 256 + tid;
            int r = idx >> 5;              // 0..15
            int c = (idx & 31) * 4;        // 0..124
            float4 v = *(const float4*)(Bg + (size_t)(k0 + r) * U + c);
            *(float4*)(Bs + r * BS_LD + c) = v;
        }
        __syncthreads();

#pragma unroll
        for (int kk = 0; kk < TILE_K; kk++) {
            const unsigned long long* ap =
                (const unsigned long long*)(As + kk * AS_LD + ty * 16);
            const unsigned long long* bp =
                (const unsigned long long*)(Bs + kk * BS_LD + tx * 8);
            unsigned long long a[8], bv[4];
#pragma unroll
            for (int i = 0; i < 8; i++) a[i] = ap[i];     // dup(A[m][kk])
#pragma unroll
            for (int j = 0; j < 4; j++) bv[j] = bp[j];    // (B[kk][2j],B[kk][2j+1])
#pragma unroll
            for (int i = 0; i < 8; i++)
#pragma unroll
                for (int j = 0; j < 4; j++)
                    acc[i][j] = ffma2(a[i], bv[j], acc[i][j]);
        }
        __syncthreads();
    }

    // ---- epilogue: tanh + W2 dot, reduce over the 16 tx lanes ----
    float dpv[8], w2v[8];
#pragma unroll
    for (int j = 0; j < 8; j++) {
        int u = u0 + tx * 8 + j;
        dpv[j] = g_dec_proj[b * U + u];
        w2v[j] = W2[u];
    }
#pragma unroll
    for (int i = 0; i < 8; i++) {
        float part = 0.f;
#pragma unroll
        for (int j = 0; j < 4; j++) {
            float2 v = unpack2(acc[i][j]);
            part += tanhf(v.x + dpv[2 * j])     * w2v[2 * j];
            part += tanhf(v.y + dpv[2 * j + 1]) * w2v[2 * j + 1];
        }
        // butterfly over tx (lanes 0..15 of each half-warp)
#pragma unroll
        for (int off = 8; off >= 1; off >>= 1)
            part += __shfl_xor_sync(0xffffffffu, part, off);
        if (tx == 0)
            atomicAdd(&g_scores[b * T + t0 + ty * 8 + i], part);
    }
}

// -------------------- kernel 3: softmax + zero context --------------------
__global__ void softmax_kernel(const float* __restrict__ b2,
                               float* __restrict__ out,
                               int B, int T, int D) {
    const int b = blockIdx.x;
    const int tid = threadIdx.x;
    __shared__ float red[256];
    const float b2v = b2[0];
    const int n = T / 256;                 // 8 for T=2048
    float sv[8];

    float mx = 0.f;                        // relu -> scores >= 0
    for (int q = 0; q < n; q++) {
        float s = g_scores[b * T + q * 256 + tid] + b2v;
        s = s > 0.f ? s : 0.f;
        sv[q] = s;
        mx = fmaxf(mx, s);
    }
    red[tid] = mx; __syncthreads();
    for (int off = 128; off >= 1; off >>= 1) {
        if (tid < off) red[tid] = fmaxf(red[tid], red[tid + off]);
        __syncthreads();
    }
    mx = red[0]; __syncthreads();

    float sum = 0.f;
    for (int q = 0; q < n; q++) {
        float e = expf(sv[q] - mx);
        sv[q] = e;
        sum += e;
    }
    red[tid] = sum; __syncthreads();
    for (int off = 128; off >= 1; off >>= 1) {
        if (tid < off) red[tid] += red[tid + off];
        __syncthreads();
    }
    const float inv = 1.f / red[0];

    float* attn = out + (size_t)B * D + (size_t)b * T;
    for (int q = 0; q < n; q++) attn[q * 256 + tid] = sv[q] * inv;

    // zero context slab (d_out is poisoned; kernel 4 accumulates with atomics)
    for (int i = tid; i < D; i += 256) out[b * D + i] = 0.f;
}

// -------------------- kernel 4: context = sum_t attn * h_enc --------------------
__global__ void context_kernel(const float* __restrict__ h_enc,
                               float* __restrict__ out,
                               int B, int T, int D) {
    const int b  = blockIdx.y;
    const int t0 = blockIdx.x * 128;
    const int tid = threadIdx.x;           // blockDim = D/4
    __shared__ float at[128];
    if (tid < 128) at[tid] = out[(size_t)B * D + (size_t)b * T + t0 + tid];
    __syncthreads();

    const int d = tid * 4;
    float4 acc = make_float4(0.f, 0.f, 0.f, 0.f);
    const float* hp = h_enc + ((size_t)b * T + t0) * D + d;
#pragma unroll 4
    for (int tt = 0; tt < 128; tt++) {
        float4 h = *(const float4*)(hp + (size_t)tt * D);
        float a = at[tt];
        acc.x += a * h.x; acc.y += a * h.y; acc.z += a * h.z; acc.w += a * h.w;
    }
    float* cp = out + (size_t)b * D + d;
    atomicAdd(cp + 0, acc.x);
    atomicAdd(cp + 1, acc.y);
    atomicAdd(cp + 2, acc.z);
    atomicAdd(cp + 3, acc.w);
}

// -------------------- host launcher --------------------
extern "C" void kernel_launch(void* const* d_in, const int* in_sizes, int n_in,
                              void* d_out, int out_size) {
    const float* h_enc = (const float*)d_in[0];
    const float* h_dec = (const float*)d_in[1];
    const float* W1    = (const float*)d_in[2];
    const float* b1    = (const float*)d_in[3];
    const float* W2    = (const float*)d_in[4];
    const float* b2    = (const float*)d_in[5];
    float* out = (float*)d_out;

    const int U = in_sizes[3];                 // 512
    const int D = in_sizes[2] / (2 * U);       // 512
    const int B = in_sizes[1] / D;             // 32
    const int T = in_sizes[0] / (B * D);       // 2048

    prep_kernel<<<B, 256>>>(h_dec, W1, b1, B, T, D, U);

    dim3 sgrid(T / TILE_M, B, U / TILE_N);     // (16, 32, 4)
    score_kernel<<<sgrid, 256>>>(h_enc, W1, W2, B, T, D, U);

    softmax_kernel<<<B, 256>>>(b2, out, B, T, D);

    dim3 cgrid(T / 128, B);                    // (16, 32)
    context_kernel<<<cgrid, D / 4>>>(h_enc, out, B, T, D);
}

// round 4
// speedup vs baseline: 2.6273x; 2.6273x over previous
#include <cuda_runtime.h>
#include <cuda_bf16.h>
#include <cstdint>

// ---------------------------------------------------------------------------
// pointwise (Bahdanau additive) attention, fp32 via split-bf16 mma.sync HMMA
// B=32, T=2048, D=512, U=512
// out layout: [0, B*D) = context ; [B*D, B*D + B*T) = attn
// ---------------------------------------------------------------------------

#define CB 32
#define CT 2048
#define CD 512
#define CU 512

// scratch (allocation-free rule: __device__ globals)
__device__ float g_scores[CB * CT];
__device__ float g_dec_proj[CB * CU];
__device__ __nv_bfloat16 g_W1hi[CU * CD];            // transposed: [u][k]
__device__ __nv_bfloat16 g_W1lo[CU * CD];
__device__ __nv_bfloat16 g_Ahi[(size_t)CB * CT * CD]; // h_enc hi split
__device__ __nv_bfloat16 g_Alo[(size_t)CB * CT * CD]; // h_enc lo split

// -------------------- PTX helpers --------------------
__device__ __forceinline__ uint32_t smem_u32(const void* p) {
    uint32_t a;
    asm("{ .reg .u64 t; cvta.to.shared.u64 t, %1; cvt.u32.u64 %0, t; }"
        : "=r"(a) : "l"(p));
    return a;
}
__device__ __forceinline__ void cp16(uint32_t dst, const void* src) {
    asm volatile("cp.async.cg.shared.global [%0], [%1], 16;"
                 :: "r"(dst), "l"(src) : "memory");
}

#define LDSM4(r, addr)                                                        \
    asm volatile("ldmatrix.sync.aligned.m8n8.x4.shared.b16 {%0,%1,%2,%3}, [%4];" \
                 : "=r"((r)[0]), "=r"((r)[1]), "=r"((r)[2]), "=r"((r)[3])     \
                 : "r"(addr))

#define MMA(d, a, b0, b1)                                                     \
    asm volatile("mma.sync.aligned.m16n8k16.row.col.f32.bf16.bf16.f32 "       \
                 "{%0,%1,%2,%3}, {%4,%5,%6,%7}, {%8,%9}, {%0,%1,%2,%3};"      \
                 : "+f"((d)[0]), "+f"((d)[1]), "+f"((d)[2]), "+f"((d)[3])     \
                 : "r"((a)[0]), "r"((a)[1]), "r"((a)[2]), "r"((a)[3]),        \
                   "r"(b0), "r"(b1))

// -------------------- kernel 0a: split h_enc into bf16 hi/lo --------------------
__global__ void hsplit_kernel(const float* __restrict__ h) {
    size_t i = (size_t)blockIdx.x * blockDim.x + threadIdx.x;  // float4 index
    float4 v = ((const float4*)h)[i];
    __nv_bfloat16 h0 = __float2bfloat16_rn(v.x);
    __nv_bfloat16 h1 = __float2bfloat16_rn(v.y);
    __nv_bfloat16 h2 = __float2bfloat16_rn(v.z);
    __nv_bfloat16 h3 = __float2bfloat16_rn(v.w);
    __nv_bfloat16 l0 = __float2bfloat16_rn(v.x - __bfloat162float(h0));
    __nv_bfloat16 l1 = __float2bfloat16_rn(v.y - __bfloat162float(h1));
    __nv_bfloat16 l2 = __float2bfloat16_rn(v.z - __bfloat162float(h2));
    __nv_bfloat16 l3 = __float2bfloat16_rn(v.w - __bfloat162float(h3));
    uint2 hv, lv;
    hv.x = (uint32_t)__bfloat16_as_ushort(h0) | ((uint32_t)__bfloat16_as_ushort(h1) << 16);
    hv.y = (uint32_t)__bfloat16_as_ushort(h2) | ((uint32_t)__bfloat16_as_ushort(h3) << 16);
    lv.x = (uint32_t)__bfloat16_as_ushort(l0) | ((uint32_t)__bfloat16_as_ushort(l1) << 16);
    lv.y = (uint32_t)__bfloat16_as_ushort(l2) | ((uint32_t)__bfloat16_as_ushort(l3) << 16);
    ((uint2*)g_Ahi)[i] = hv;
    ((uint2*)g_Alo)[i] = lv;
}

// -------------------- kernel 0b: transpose+split W1_enc --------------------
__global__ void w1conv_kernel(const float* __restrict__ W1) {
    __shared__ float t[32][33];
    const int tx = threadIdx.x, ty = threadIdx.y;   // (32, 8)
    const int u0 = blockIdx.x * 32, k0 = blockIdx.y * 32;
#pragma unroll
    for (int i = 0; i < 4; i++)
        t[ty + i * 8][tx] = W1[(size_t)(k0 + ty + i * 8) * CU + u0 + tx];
    __syncthreads();
#pragma unroll
    for (int i = 0; i < 4; i++) {
        int u = u0 + ty + i * 8, k = k0 + tx;
        float v = t[tx][ty + i * 8];
        __nv_bfloat16 h = __float2bfloat16_rn(v);
        g_W1hi[(size_t)u * CD + k] = h;
        g_W1lo[(size_t)u * CD + k] = __float2bfloat16_rn(v - __bfloat162float(h));
    }
}

// -------------------- kernel 1: dec projection + zero scores --------------------
__global__ void prep_kernel(const float* __restrict__ h_dec,
                            const float* __restrict__ W1,
                            const float* __restrict__ b1) {
    const int b = blockIdx.x;
    __shared__ float hd[CD];
    for (int i = threadIdx.x; i < CD; i += blockDim.x) hd[i] = h_dec[b * CD + i];
    __syncthreads();

    for (int u = threadIdx.x; u < CU; u += blockDim.x) {
        float acc0 = b1[u], acc1 = 0.f, acc2 = 0.f, acc3 = 0.f;
        for (int k = 0; k < CD; k += 4) {
            acc0 += hd[k + 0] * W1[(size_t)(CD + k + 0) * CU + u];
            acc1 += hd[k + 1] * W1[(size_t)(CD + k + 1) * CU + u];
            acc2 += hd[k + 2] * W1[(size_t)(CD + k + 2) * CU + u];
            acc3 += hd[k + 3] * W1[(size_t)(CD + k + 3) * CU + u];
        }
        g_dec_proj[b * CU + u] = (acc0 + acc1) + (acc2 + acc3);
    }
    for (int t = threadIdx.x; t < CT; t += blockDim.x) g_scores[b * CT + t] = 0.f;
}

// -------------------- kernel 2: HMMA split-bf16 score GEMM --------------------
// CTA tile: 128 t-rows x 128 u-cols, K=512 in 8 chunks of 64, 2-stage cp.async.
// smem stage (64KB): Ahi | Alo | Bhi | Blo, each 128x64 bf16 (16KB), swizzled.
#define SM_STAGE 65536
#define SM_ALO 16384
#define SM_BHI 32768
#define SM_BLO 49152
#define SM_DP  131072
#define SM_W2  131584
#define SM_TOT 132096

__global__ __launch_bounds__(256)
void score_kernel(const float* __restrict__ W2) {
    extern __shared__ char smem[];
    const uint32_t sbase = smem_u32(smem);
    const int tid = threadIdx.x;
    const int wid = tid >> 5, lid = tid & 31;
    const int wm = wid >> 1, wn = wid & 1;
    const int b = blockIdx.y;
    const int ut = blockIdx.x & 3, tt = blockIdx.x >> 2;
    const int t0 = tt * 128, u0 = ut * 128;
    const size_t rowA0 = (size_t)b * CT + t0;

    float* sdp = (float*)(smem + SM_DP);
    float* sw2 = (float*)(smem + SM_W2);
    if (tid < 128) {
        sdp[tid] = g_dec_proj[b * CU + u0 + tid];
        sw2[tid] = W2[u0 + tid];
    }

    // per-lane ldmatrix geometry
    const int rowAf = wm * 32 + (lid & 7) + ((lid >> 3) & 1) * 8;
    const int kselA = lid >> 4;
    const int rowBf = wn * 64 + (lid & 7) + (lid >> 4) * 8;
    const int kselB = (lid >> 3) & 1;
    const int swz = lid & 7;                       // row&7 for both (offsets are mult of 8/16)

    float acc[2][8][4];
#pragma unroll
    for (int mt = 0; mt < 2; mt++)
#pragma unroll
        for (int nt = 0; nt < 8; nt++)
#pragma unroll
            for (int j = 0; j < 4; j++) acc[mt][nt][j] = 0.f;

    // cp.async loader for K-chunk c into stage c&1
    auto load_chunk = [&](int c) {
        const int k0 = c * 64;
        const uint32_t sb = sbase + (c & 1) * SM_STAGE;
#pragma unroll
        for (int q = 0; q < 4; q++) {
            int idx = q * 256 + tid;
            int row = idx >> 3, ch = idx & 7;
            uint32_t doff = row * 128 + ((ch ^ (row & 7)) << 4);
            size_t aoff = (rowA0 + row) * CD + k0 + ch * 8;
            size_t boff = (size_t)(u0 + row) * CD + k0 + ch * 8;
            cp16(sb + doff,          g_Ahi + aoff);
            cp16(sb + SM_ALO + doff, g_Alo + aoff);
            cp16(sb + SM_BHI + doff, g_W1hi + boff);
            cp16(sb + SM_BLO + doff, g_W1lo + boff);
        }
    };

    load_chunk(0);
    asm volatile("cp.async.commit_group;" ::: "memory");

    for (int c = 0; c < 8; c++) {
        if (c < 7) {
            load_chunk(c + 1);
            asm volatile("cp.async.commit_group;" ::: "memory");
            asm volatile("cp.async.wait_group 1;" ::: "memory");
        } else {
            asm volatile("cp.async.wait_group 0;" ::: "memory");
        }
        __syncthreads();

        const uint32_t sb = sbase + (c & 1) * SM_STAGE;
#pragma unroll
        for (int ks = 0; ks < 4; ks++) {
            uint32_t aH[2][4], aL[2][4];
#pragma unroll
            for (int mt = 0; mt < 2; mt++) {
                uint32_t addr = sb + (rowAf + mt * 16) * 128 +
                                (((ks * 2 + kselA) ^ swz) << 4);
                LDSM4(aH[mt], addr);
                LDSM4(aL[mt], addr + SM_ALO);
            }
#pragma unroll
            for (int ng = 0; ng < 4; ng++) {
                uint32_t baddr = sb + SM_BHI + (rowBf + ng * 16) * 128 +
                                 (((ks * 2 + kselB) ^ swz) << 4);
                uint32_t bH[4], bL[4];
                LDSM4(bH, baddr);
                LDSM4(bL, baddr + 16384);
#pragma unroll
                for (int mt = 0; mt < 2; mt++) {
                    MMA(acc[mt][2 * ng],     aH[mt], bH[0], bH[1]);
                    MMA(acc[mt][2 * ng],     aH[mt], bL[0], bL[1]);
                    MMA(acc[mt][2 * ng],     aL[mt], bH[0], bH[1]);
                    MMA(acc[mt][2 * ng + 1], aH[mt], bH[2], bH[3]);
                    MMA(acc[mt][2 * ng + 1], aH[mt], bL[2], bL[3]);
                    MMA(acc[mt][2 * ng + 1], aL[mt], bH[2], bH[3]);
                }
            }
        }
        __syncthreads();
    }

    // ---- epilogue: scores[row] += sum_u tanh(acc + dp[u]) * w2[u] ----
    const int lid4 = lid & 3, lg = lid >> 2;
    const int ulb = wn * 64 + lid4 * 2;
#pragma unroll
    for (int mt = 0; mt < 2; mt++) {
        float s0 = 0.f, s1 = 0.f;
#pragma unroll
        for (int nt = 0; nt < 8; nt++) {
            int ul = ulb + nt * 8;
            float d0 = sdp[ul], d1 = sdp[ul + 1];
            float w0 = sw2[ul], w1 = sw2[ul + 1];
            s0 += tanhf(acc[mt][nt][0] + d0) * w0 + tanhf(acc[mt][nt][1] + d1) * w1;
            s1 += tanhf(acc[mt][nt][2] + d0) * w0 + tanhf(acc[mt][nt][3] + d1) * w1;
        }
        s0 += __shfl_xor_sync(0xffffffffu, s0, 1);
        s0 += __shfl_xor_sync(0xffffffffu, s0, 2);
        s1 += __shfl_xor_sync(0xffffffffu, s1, 1);
        s1 += __shfl_xor_sync(0xffffffffu, s1, 2);
        if (lid4 == 0) {
            int r = wm * 32 + mt * 16 + lg;
            atomicAdd(&g_scores[b * CT + t0 + r], s0);
            atomicAdd(&g_scores[b * CT + t0 + r + 8], s1);
        }
    }
}

// -------------------- kernel 3: softmax (+ b2, relu) + zero context --------------------
__global__ void softmax_kernel(const float* __restrict__ b2, float* __restrict__ out) {
    const int b = blockIdx.x;
    const int tid = threadIdx.x;
    __shared__ float red[256];
    const float b2v = b2[0];
    float sv[8];

    float mx = 0.f;                        // relu -> scores >= 0
#pragma unroll
    for (int q = 0; q < 8; q++) {
        float s = g_scores[b * CT + q * 256 + tid] + b2v;
        s = s > 0.f ? s : 0.f;
        sv[q] = s;
        mx = fmaxf(mx, s);
    }
    red[tid] = mx; __syncthreads();
    for (int off = 128; off >= 1; off >>= 1) {
        if (tid < off) red[tid] = fmaxf(red[tid], red[tid + off]);
        __syncthreads();
    }
    mx = red[0]; __syncthreads();

    float sum = 0.f;
#pragma unroll
    for (int q = 0; q < 8; q++) {
        float e = expf(sv[q] - mx);
        sv[q] = e;
        sum += e;
    }
    red[tid] = sum; __syncthreads();
    for (int off = 128; off >= 1; off >>= 1) {
        if (tid < off) red[tid] += red[tid + off];
        __syncthreads();
    }
    const float inv = 1.f / red[0];

    float* attn = out + (size_t)CB * CD + (size_t)b * CT;
#pragma unroll
    for (int q = 0; q < 8; q++) attn[q * 256 + tid] = sv[q] * inv;

    for (int i = tid; i < CD; i += 256) out[b * CD + i] = 0.f;
}

// -------------------- kernel 4: context = sum_t attn * h_enc --------------------
__global__ void context_kernel(const float* __restrict__ h_enc, float* __restrict__ out) {
    const int b = blockIdx.y;
    const int t0 = blockIdx.x * 128;
    const int tid = threadIdx.x;           // 128 threads (D/4)
    __shared__ float at[128];
    if (tid < 128) at[tid] = out[(size_t)CB * CD + (size_t)b * CT + t0 + tid];
    __syncthreads();

    const int d = tid * 4;
    float4 acc = make_float4(0.f, 0.f, 0.f, 0.f);
    const float* hp = h_enc + ((size_t)b * CT + t0) * CD + d;
#pragma unroll 4
    for (int tt = 0; tt < 128; tt++) {
        float4 h = *(const float4*)(hp + (size_t)tt * CD);
        float a = at[tt];
        acc.x += a * h.x; acc.y += a * h.y; acc.z += a * h.z; acc.w += a * h.w;
    }
    float* cp = out + (size_t)b * CD + d;
    atomicAdd(cp + 0, acc.x);
    atomicAdd(cp + 1, acc.y);
    atomicAdd(cp + 2, acc.z);
    atomicAdd(cp + 3, acc.w);
}

// -------------------- host launcher --------------------
extern "C" void kernel_launch(void* const* d_in, const int* in_sizes, int n_in,
                              void* d_out, int out_size) {
    const float* h_enc = (const float*)d_in[0];
    const float* h_dec = (const float*)d_in[1];
    const float* W1    = (const float*)d_in[2];
    const float* b1    = (const float*)d_in[3];
    const float* W2    = (const float*)d_in[4];
    const float* b2    = (const float*)d_in[5];
    float* out = (float*)d_out;

    cudaFuncSetAttribute(score_kernel,
                         cudaFuncAttributeMaxDynamicSharedMemorySize, SM_TOT);

    hsplit_kernel<<<(CB * CT * CD / 4) / 256, 256>>>(h_enc);
    w1conv_kernel<<<dim3(CU / 32, CD / 32), dim3(32, 8)>>>(W1);
    prep_kernel<<<CB, 256>>>(h_dec, W1, b1);
    score_kernel<<<dim3(64, CB), 256, SM_TOT>>>(W2);
    softmax_kernel<<<CB, 256>>>(b2, out);
    context_kernel<<<dim3(CT / 128, CB), 128>>>(h_enc, out);
}

// round 5
// speedup vs baseline: 2.8721x; 1.0932x over previous
#include <cuda_runtime.h>
#include <cuda_bf16.h>
#include <cstdint>

// ---------------------------------------------------------------------------
// pointwise (Bahdanau additive) attention, fp32 via split-bf16 mma.sync HMMA
// B=32, T=2048, D=512, U=512
// out layout: [0, B*D) = context ; [B*D, B*D + B*T) = attn
// Round 5: persistent score kernel, in-kernel A split, fast tanh, MLP context
// ---------------------------------------------------------------------------

#define CB 32
#define CT 2048
#define CD 512
#define CU 512
#define NTILES 2048              // 32 b x 16 t-tiles x 4 u-tiles
#define GRID_P 148               // persistent CTAs

// scratch (allocation-free rule: __device__ globals)
__device__ float g_scores[CB * CT];
__device__ float g_dec_proj[CB * CU];
__device__ __nv_bfloat16 g_W1hi[CU * CD];   // transposed: [u][k]
__device__ __nv_bfloat16 g_W1lo[CU * CD];

// -------------------- PTX helpers --------------------
__device__ __forceinline__ uint32_t smem_u32(const void* p) {
    uint32_t a;
    asm("{ .reg .u64 t; cvta.to.shared.u64 t, %1; cvt.u32.u64 %0, t; }"
        : "=r"(a) : "l"(p));
    return a;
}
__device__ __forceinline__ void cp16(uint32_t dst, const void* src) {
    asm volatile("cp.async.cg.shared.global [%0], [%1], 16;"
                 :: "r"(dst), "l"(src) : "memory");
}
// Dekker split of (a,b) -> packed bf16x2 hi + bf16x2 lo
__device__ __forceinline__ void split2(float a, float b, uint32_t& hi, uint32_t& lo) {
    asm("cvt.rn.bf16x2.f32 %0, %1, %2;" : "=r"(hi) : "f"(b), "f"(a)); // low=a, high=b
    float ha = __uint_as_float(hi << 16);
    float hb = __uint_as_float(hi & 0xffff0000u);
    float la = a - ha, lb = b - hb;
    asm("cvt.rn.bf16x2.f32 %0, %1, %2;" : "=r"(lo) : "f"(lb), "f"(la));
}
__device__ __forceinline__ float fast_tanh(float x) {
    float e;
    asm("ex2.approx.f32 %0, %1;" : "=f"(e) : "f"(x * 2.885390081777927f)); // e^(2x)
    float r;
    asm("rcp.approx.f32 %0, %1;" : "=f"(r) : "f"(e + 1.0f));
    return fmaf(-2.0f, r, 1.0f);
}

#define LDSM4(r, addr)                                                        \
    asm volatile("ldmatrix.sync.aligned.m8n8.x4.shared.b16 {%0,%1,%2,%3}, [%4];" \
                 : "=r"((r)[0]), "=r"((r)[1]), "=r"((r)[2]), "=r"((r)[3])     \
                 : "r"(addr))

#define MMA(d, a, b0, b1)                                                     \
    asm volatile("mma.sync.aligned.m16n8k16.row.col.f32.bf16.bf16.f32 "       \
                 "{%0,%1,%2,%3}, {%4,%5,%6,%7}, {%8,%9}, {%0,%1,%2,%3};"      \
                 : "+f"((d)[0]), "+f"((d)[1]), "+f"((d)[2]), "+f"((d)[3])     \
                 : "r"((a)[0]), "r"((a)[1]), "r"((a)[2]), "r"((a)[3]),        \
                   "r"(b0), "r"(b1))

// -------------------- kernel 0: transpose+split W1_enc --------------------
__global__ void w1conv_kernel(const float* __restrict__ W1) {
    __shared__ float t[32][33];
    const int tx = threadIdx.x, ty = threadIdx.y;   // (32, 8)
    const int u0 = blockIdx.x * 32, k0 = blockIdx.y * 32;
#pragma unroll
    for (int i = 0; i < 4; i++)
        t[ty + i * 8][tx] = W1[(size_t)(k0 + ty + i * 8) * CU + u0 + tx];
    __syncthreads();
#pragma unroll
    for (int i = 0; i < 4; i++) {
        int u = u0 + ty + i * 8, k = k0 + tx;
        float v = t[tx][ty + i * 8];
        __nv_bfloat16 h = __float2bfloat16_rn(v);
        g_W1hi[(size_t)u * CD + k] = h;
        g_W1lo[(size_t)u * CD + k] = __float2bfloat16_rn(v - __bfloat162float(h));
    }
}

// -------------------- kernel 1: dec projection + zero scores --------------------
__global__ void prep_kernel(const float* __restrict__ h_dec,
                            const float* __restrict__ W1,
                            const float* __restrict__ b1) {
    const int b = blockIdx.x;
    __shared__ float hd[CD];
    for (int i = threadIdx.x; i < CD; i += blockDim.x) hd[i] = h_dec[b * CD + i];
    __syncthreads();

    for (int u = threadIdx.x; u < CU; u += blockDim.x) {
        float acc0 = b1[u], acc1 = 0.f, acc2 = 0.f, acc3 = 0.f;
        for (int k = 0; k < CD; k += 4) {
            acc0 += hd[k + 0] * W1[(size_t)(CD + k + 0) * CU + u];
            acc1 += hd[k + 1] * W1[(size_t)(CD + k + 1) * CU + u];
            acc2 += hd[k + 2] * W1[(size_t)(CD + k + 2) * CU + u];
            acc3 += hd[k + 3] * W1[(size_t)(CD + k + 3) * CU + u];
        }
        g_dec_proj[b * CU + u] = (acc0 + acc1) + (acc2 + acc3);
    }
    for (int t = threadIdx.x; t < CT; t += blockDim.x) g_scores[b * CT + t] = 0.f;
}

// -------------------- kernel 2: persistent HMMA split-bf16 score GEMM --------------------
// tile = 128 t-rows x 128 u-cols x K=512 (8 chunks of 64). Stage (64KB):
// Ahi | Alo | Bhi | Blo, each 128x64 bf16 (16KB), XOR-swizzled 128B rows. 2 stages.
#define SM_STAGE 65536
#define SM_ALO 16384
#define SM_BHI 32768
#define SM_BLO 49152
#define SM_DP  131072
#define SM_W2  131584
#define SM_TOT 132096

__global__ __launch_bounds__(256, 1)
void score_kernel(const float* __restrict__ h_enc, const float* __restrict__ W2) {
    extern __shared__ char smem[];
    const uint32_t sbase = smem_u32(smem);
    const int tid = threadIdx.x;
    const int wid = tid >> 5, lid = tid & 31;
    const int wm = wid >> 1, wn = wid & 1;

    // per-lane ldmatrix geometry
    const int rowAf = wm * 32 + (lid & 7) + ((lid >> 3) & 1) * 8;
    const int kselA = lid >> 4;
    const int rowBf = wn * 64 + (lid & 7) + (lid >> 4) * 8;
    const int kselB = (lid >> 3) & 1;
    const int swz = lid & 7;

    float* sdp = (float*)(smem + SM_DP);
    float* sw2 = (float*)(smem + SM_W2);

    float4 ra[8];

    // ---- lambdas -----------------------------------------------------------
    auto ldgA = [&](int tix_, int c) {
        const int b_ = tix_ >> 6, tt_ = (tix_ >> 2) & 15;
        const float* Ag = h_enc + ((size_t)(b_ * CT + tt_ * 128)) * CD + c * 64;
#pragma unroll
        for (int q = 0; q < 4; q++) {
            int idx = q * 256 + tid;
            int row = idx >> 3, pair = idx & 7;
            const float4* p = (const float4*)(Ag + (size_t)row * CD + pair * 8);
            ra[2 * q] = p[0];
            ra[2 * q + 1] = p[1];
        }
    };
    auto stsA = [&](int st) {
        char* sb = smem + st * SM_STAGE;
#pragma unroll
        for (int q = 0; q < 4; q++) {
            int idx = q * 256 + tid;
            int row = idx >> 3, pair = idx & 7;
            uint32_t doff = row * 128 + ((pair ^ (row & 7)) << 4);
            float4 v0 = ra[2 * q], v1 = ra[2 * q + 1];
            uint4 hv, lv;
            split2(v0.x, v0.y, hv.x, lv.x);
            split2(v0.z, v0.w, hv.y, lv.y);
            split2(v1.x, v1.y, hv.z, lv.z);
            split2(v1.z, v1.w, hv.w, lv.w);
            *(uint4*)(sb + doff) = hv;
            *(uint4*)(sb + SM_ALO + doff) = lv;
        }
    };
    auto cpB = [&](int tix_, int c, int st) {
        const int u0_ = (tix_ & 3) * 128;
        const int k0 = c * 64;
        const uint32_t sb = sbase + st * SM_STAGE;
#pragma unroll
        for (int q = 0; q < 4; q++) {
            int idx = q * 256 + tid;
            int row = idx >> 3, ch = idx & 7;
            uint32_t doff = row * 128 + ((ch ^ (row & 7)) << 4);
            size_t boff = (size_t)(u0_ + row) * CD + k0 + ch * 8;
            cp16(sb + SM_BHI + doff, g_W1hi + boff);
            cp16(sb + SM_BLO + doff, g_W1lo + boff);
        }
    };
    auto loadDW = [&](int tix_) {
        const int b_ = tix_ >> 6, u0_ = (tix_ & 3) * 128;
        if (tid < 128) {
            sdp[tid] = g_dec_proj[b_ * CU + u0_ + tid];
            sw2[tid] = W2[u0_ + tid];
        }
    };

    // ---- prologue ----------------------------------------------------------
    int tix = blockIdx.x;
    ldgA(tix, 0);
    cpB(tix, 0, 0);
    asm volatile("cp.async.commit_group;" ::: "memory");
    loadDW(tix);

    float acc[2][8][4];
    int stage = 0;

    for (; tix < NTILES; tix += GRID_P) {
        const int b = tix >> 6;
        const int t0 = ((tix >> 2) & 15) * 128;
#pragma unroll
        for (int mt = 0; mt < 2; mt++)
#pragma unroll
            for (int nt = 0; nt < 8; nt++)
#pragma unroll
                for (int j = 0; j < 4; j++) acc[mt][nt][j] = 0.f;

#pragma unroll 1
        for (int c = 0; c < 8; c++) {
            asm volatile("cp.async.wait_group 0;" ::: "memory");
            stsA(stage);
            __syncthreads();

            // prefetch next chunk (possibly next tile's chunk 0)
            int nc = c + 1, ntix = tix;
            if (nc == 8) { nc = 0; ntix += GRID_P; }
            if (ntix < NTILES) {
                cpB(ntix, nc, stage ^ 1);
                asm volatile("cp.async.commit_group;" ::: "memory");
                ldgA(ntix, nc);
            }

            // ---- compute chunk ----
            const uint32_t sb = sbase + stage * SM_STAGE;
#pragma unroll
            for (int ks = 0; ks < 4; ks++) {
                uint32_t aH[2][4], aL[2][4];
#pragma unroll
                for (int mt = 0; mt < 2; mt++) {
                    uint32_t addr = sb + (rowAf + mt * 16) * 128 +
                                    (((ks * 2 + kselA) ^ swz) << 4);
                    LDSM4(aH[mt], addr);
                    LDSM4(aL[mt], addr + SM_ALO);
                }
#pragma unroll
                for (int ng = 0; ng < 4; ng++) {
                    uint32_t baddr = sb + SM_BHI + (rowBf + ng * 16) * 128 +
                                     (((ks * 2 + kselB) ^ swz) << 4);
                    uint32_t bH[4], bL[4];
                    LDSM4(bH, baddr);
                    LDSM4(bL, baddr + 16384);
#pragma unroll
                    for (int mt = 0; mt < 2; mt++) {
                        MMA(acc[mt][2 * ng],     aH[mt], bH[0], bH[1]);
                        MMA(acc[mt][2 * ng],     aH[mt], bL[0], bL[1]);
                        MMA(acc[mt][2 * ng],     aL[mt], bH[0], bH[1]);
                        MMA(acc[mt][2 * ng + 1], aH[mt], bH[2], bH[3]);
                        MMA(acc[mt][2 * ng + 1], aH[mt], bL[2], bL[3]);
                        MMA(acc[mt][2 * ng + 1], aL[mt], bH[2], bH[3]);
                    }
                }
            }
            stage ^= 1;
        }

        // ---- epilogue: scores[row] += sum_u tanh(acc + dp[u]) * w2[u] ----
        const int lid4 = lid & 3, lg = lid >> 2;
        const int ulb = wn * 64 + lid4 * 2;
#pragma unroll
        for (int mt = 0; mt < 2; mt++) {
            float s0 = 0.f, s1 = 0.f;
#pragma unroll
            for (int nt = 0; nt < 8; nt++) {
                int ul = ulb + nt * 8;
                float d0 = sdp[ul], d1 = sdp[ul + 1];
                float w0 = sw2[ul], w1 = sw2[ul + 1];
                s0 += fast_tanh(acc[mt][nt][0] + d0) * w0 +
                      fast_tanh(acc[mt][nt][1] + d1) * w1;
                s1 += fast_tanh(acc[mt][nt][2] + d0) * w0 +
                      fast_tanh(acc[mt][nt][3] + d1) * w1;
            }
            s0 += __shfl_xor_sync(0xffffffffu, s0, 1);
            s0 += __shfl_xor_sync(0xffffffffu, s0, 2);
            s1 += __shfl_xor_sync(0xffffffffu, s1, 1);
            s1 += __shfl_xor_sync(0xffffffffu, s1, 2);
            if (lid4 == 0) {
                int r = wm * 32 + mt * 16 + lg;
                atomicAdd(&g_scores[b * CT + t0 + r], s0);
                atomicAdd(&g_scores[b * CT + t0 + r + 8], s1);
            }
        }
        __syncthreads();                 // all warps done reading sdp/sw2
        if (tix + GRID_P < NTILES) loadDW(tix + GRID_P);
    }
}

// -------------------- kernel 3: softmax (+ b2, relu) + zero context --------------------
__global__ void softmax_kernel(const float* __restrict__ b2, float* __restrict__ out) {
    const int b = blockIdx.x;
    const int tid = threadIdx.x;
    __shared__ float red[256];
    const float b2v = b2[0];
    float sv[8];

    float mx = 0.f;                        // relu -> scores >= 0
#pragma unroll
    for (int q = 0; q < 8; q++) {
        float s = g_scores[b * CT + q * 256 + tid] + b2v;
        s = s > 0.f ? s : 0.f;
        sv[q] = s;
        mx = fmaxf(mx, s);
    }
    red[tid] = mx; __syncthreads();
    for (int off = 128; off >= 1; off >>= 1) {
        if (tid < off) red[tid] = fmaxf(red[tid], red[tid + off]);
        __syncthreads();
    }
    mx = red[0]; __syncthreads();

    float sum = 0.f;
#pragma unroll
    for (int q = 0; q < 8; q++) {
        float e = expf(sv[q] - mx);
        sv[q] = e;
        sum += e;
    }
    red[tid] = sum; __syncthreads();
    for (int off = 128; off >= 1; off >>= 1) {
        if (tid < off) red[tid] += red[tid + off];
        __syncthreads();
    }
    const float inv = 1.f / red[0];

    float* attn = out + (size_t)CB * CD + (size_t)b * CT;
#pragma unroll
    for (int q = 0; q < 8; q++) attn[q * 256 + tid] = sv[q] * inv;

    for (int i = tid; i < CD; i += 256) out[b * CD + i] = 0.f;
}

// -------------------- kernel 4: context = sum_t attn * h_enc --------------------
__global__ void context_kernel(const float* __restrict__ h_enc, float* __restrict__ out) {
    const int b = blockIdx.y;
    const int t0 = blockIdx.x * 128;
    const int tid = threadIdx.x;           // 128 threads (D/4)
    __shared__ float at[128];
    if (tid < 128) at[tid] = out[(size_t)CB * CD + (size_t)b * CT + t0 + tid];
    __syncthreads();

    const int d = tid * 4;
    float4 acc[4];
#pragma unroll
    for (int j = 0; j < 4; j++) acc[j] = make_float4(0.f, 0.f, 0.f, 0.f);
    const float* hp = h_enc + ((size_t)b * CT + t0) * CD + d;

#pragma unroll 1
    for (int tt = 0; tt < 128; tt += 16) {
        float4 h[16];
#pragma unroll
        for (int j = 0; j < 16; j++)
            h[j] = *(const float4*)(hp + (size_t)(tt + j) * CD);
        float a[16];
#pragma unroll
        for (int j = 0; j < 16; j++) a[j] = at[tt + j];
#pragma unroll
        for (int j = 0; j < 16; j++) {
            acc[j & 3].x += a[j] * h[j].x;
            acc[j & 3].y += a[j] * h[j].y;
            acc[j & 3].z += a[j] * h[j].z;
            acc[j & 3].w += a[j] * h[j].w;
        }
    }
    float4 r;
    r.x = (acc[0].x + acc[1].x) + (acc[2].x + acc[3].x);
    r.y = (acc[0].y + acc[1].y) + (acc[2].y + acc[3].y);
    r.z = (acc[0].z + acc[1].z) + (acc[2].z + acc[3].z);
    r.w = (acc[0].w + acc[1].w) + (acc[2].w + acc[3].w);
    float* cp = out + (size_t)b * CD + d;
    atomicAdd(cp + 0, r.x);
    atomicAdd(cp + 1, r.y);
    atomicAdd(cp + 2, r.z);
    atomicAdd(cp + 3, r.w);
}

// -------------------- host launcher --------------------
extern "C" void kernel_launch(void* const* d_in, const int* in_sizes, int n_in,
                              void* d_out, int out_size) {
    const float* h_enc = (const float*)d_in[0];
    const float* h_dec = (const float*)d_in[1];
    const float* W1    = (const float*)d_in[2];
    const float* b1    = (const float*)d_in[3];
    const float* W2    = (const float*)d_in[4];
    const float* b2    = (const float*)d_in[5];
    float* out = (float*)d_out;

    cudaFuncSetAttribute(score_kernel,
                         cudaFuncAttributeMaxDynamicSharedMemorySize, SM_TOT);

    w1conv_kernel<<<dim3(CU / 32, CD / 32), dim3(32, 8)>>>(W1);
    prep_kernel<<<CB, 256>>>(h_dec, W1, b1);
    score_kernel<<<GRID_P, 256, SM_TOT>>>(h_enc, W2);
    softmax_kernel<<<CB, 256>>>(b2, out);
    context_kernel<<<dim3(CT / 128, CB), 128>>>(h_enc, out);
}